// round 8
// baseline (speedup 1.0000x reference)
#include <cuda_runtime.h>

#define NS 64
#define NB 8192
#define HP 128
#define HH 64
#define NR 11
#define RC 231
#define GAPN 10
#define MCN 10000
#define DT (1.0f/64.0f)

__device__ int   g_hist[NR*20];
__device__ __align__(16) float g_wtab[RC*HP];
__device__ __align__(16) float g_A[NS*RC*HH];
__device__ __align__(16) float g_B[NS*RC];
__device__ __align__(16) float g_W3[NS*NR*6*HH];
__device__ __align__(16) float g_b3[NS*NR*6];
__device__ float4 g_P1[NS*6*32];
__device__ float4 g_P2[NS*HH*32];
__device__ float4 g_Pb[NS*32];
__device__ float4 g_Pb2[NS*32];

__global__ void kz(){ int i=threadIdx.x; if(i<NR*20) g_hist[i]=0; }

__global__ void kh(const float* __restrict__ mc, const float* __restrict__ jm){
  __shared__ int sh[NR*20];
  int tid=threadIdx.x;
  if(tid<NR*20) sh[tid]=0;
  __syncthreads();
  int i=blockIdx.x*blockDim.x+tid;
  if(i<MCN*NR){
    int r=i%NR; float u=mc[i]; const float* row=jm+r*20; int c=0;
    #pragma unroll
    for(int j=0;j<20;j++) c += (u<row[j]) ? 1 : 0;
    atomicAdd(&sh[r*20+(20-c)],1);
  }
  __syncthreads();
  if(tid<NR*20 && sh[tid]) atomicAdd(&g_hist[tid],sh[tid]);
}

__global__ void kw(const float* __restrict__ jl, const float* __restrict__ jr,
                   const float* __restrict__ cr){
  int r=blockIdx.x/21, c=blockIdx.x%21, p=threadIdx.x;
  float acc=0.f;
  #pragma unroll
  for(int k=0;k<GAPN;k++){
    acc += (float)g_hist[r*20+k]    * jl[k*HP+p];
    acc += (float)g_hist[r*20+10+k] * jl[(GAPN+k)*HP+p];
  }
  float mc_ = cr[r]*(acc*(1.0f/MCN));
  int d=c-10; float j=0.f;
  if(d>0) j=jl[(d-1)*HP+p]; else if(d<0) j=jl[(GAPN+(-d-1))*HP+p];
  g_wtab[(r*21+c)*HP+p] = jr[r*HP+p]*(j - mc_*DT);
}

// A[t][rc][h] = Wf3[t] . wtab[rc],  B[t][rc] = bf3[t] . wtab[rc]
__global__ void __launch_bounds__(256) kA2B(const float* __restrict__ Wf3,
                                            const float* __restrict__ bf3){
  int t=blockIdx.x, chunk=blockIdx.y;
  __shared__ float sW[HP*65];
  __shared__ float swt[4][HP];
  __shared__ float sb[HP];
  int tid=threadIdx.x;
  for(int idx=tid; idx<HH*HP; idx+=256){
    int h=idx>>7, p=idx&127;
    sW[p*65+h]=Wf3[t*HH*HP+idx];
  }
  if(tid<HP) sb[tid]=bf3[t*HP+tid];
  __syncthreads();
  int h=tid&63, g=tid>>6;
  int rcEnd=min(chunk*29+29,RC);
  for(int rc0=chunk*29; rc0<rcEnd; rc0+=4){
    __syncthreads();
    for(int idx=tid; idx<4*HP; idx+=256){
      int gg=idx>>7, p=idx&127; int rc=rc0+gg;
      swt[gg][p] = (rc<RC) ? g_wtab[rc*HP+p] : 0.f;
    }
    __syncthreads();
    int rc=rc0+g;
    if(rc<rcEnd){
      float a=0.f;
      #pragma unroll 8
      for(int p=0;p<HP;p++) a += sW[p*65+h]*swt[g][p];
      g_A[(t*RC+rc)*HH+h]=a;
    }
    if(tid<4 && rc0+tid<rcEnd){
      float b0=0.f,b1=0.f;
      #pragma unroll 8
      for(int p=0;p<HP;p+=2){ b0+=sb[p]*swt[tid][p]; b1+=sb[p+1]*swt[tid][p+1]; }
      g_B[t*RC+rc0+tid]=b0+b1;
    }
  }
}

// kE + kP merged
__global__ void __launch_bounds__(384) kEP(const float* __restrict__ W3,
                                           const float* __restrict__ emb,
                                           const float* __restrict__ b3,
  const float* __restrict__ W1, const float* __restrict__ b1,
  const float* __restrict__ W2, const float* __restrict__ b2,
  const float* __restrict__ Wf1, const float* __restrict__ bf1,
  const float* __restrict__ Wf2, const float* __restrict__ bf2){
  int t=blockIdx.x, tid=threadIdx.x;
  __shared__ float se[NR*HP];
  for(int i=tid;i<NR*HP;i+=384) se[i]=emb[t*NR*HP+i];
  __syncthreads();
  int h=tid/6, o=tid-h*6;
  float acc[NR];
  #pragma unroll
  for(int r=0;r<NR;r++) acc[r]=0.f;
  const float* W=W3+t*HH*768+h*768+o;
  for(int p=0;p<HP;p++){
    float wv=W[p*6];
    #pragma unroll
    for(int r=0;r<NR;r++) acc[r] += se[r*HP+p]*wv;
  }
  #pragma unroll
  for(int r=0;r<NR;r++) g_W3[((t*NR+r)*6+o)*HH+h]=acc[r];
  if(tid<6){
    float a2[NR];
    #pragma unroll
    for(int r=0;r<NR;r++) a2[r]=0.f;
    const float* bb=b3+t*768+tid;
    for(int p=0;p<HP;p++){
      float bv=bb[p*6];
      #pragma unroll
      for(int r=0;r<NR;r++) a2[r] += se[r*HP+p]*bv;
    }
    #pragma unroll
    for(int r=0;r<NR;r++) g_b3[(t*NR+r)*6+tid]=a2[r];
  }
  // ---- pack (kP) ----
  for(int idx=tid; idx<HH*32; idx+=384){
    int i=idx>>5, l=idx&31; int b=t*HH*HH+i*HH+2*l;
    g_P2[(t*HH+i)*32+l]=make_float4(W2[b],W2[b+1],Wf2[b],Wf2[b+1]);
  }
  for(int idx=tid; idx<6*32; idx+=384){
    int i=idx>>5, l=idx&31; int b=t*6*HH+i*HH+2*l;
    g_P1[(t*6+i)*32+l]=make_float4(W1[b],W1[b+1],Wf1[b],Wf1[b+1]);
  }
  if(tid<32){
    int b=t*HH+2*tid;
    g_Pb [t*32+tid]=make_float4(b1[b],b1[b+1],bf1[b],bf1[b+1]);
    g_Pb2[t*32+tid]=make_float4(b2[b],b2[b+1],bf2[b],bf2[b+1]);
  }
}

__device__ __forceinline__ float tanh_(float x){
  float e=__expf(2.f*x); return 1.f-__fdividef(2.f,e+1.f);
}

struct PS {
  int rt; int act;
  float xt[3], xi[3], yi[3];
  float gx[9], gy[9];
  float up, fun;
};

__device__ __forceinline__ void refl(float* p, float* m){
  float nr=sqrtf(p[0]*p[0]+p[1]*p[1]+p[2]*p[2]);
  if(nr>5.0f){
    float d=fmaxf(nr,1e-12f);
    float n0=p[0]/d, n1=p[1]/d, n2=p[2]/d;
    float s=10.0f-nr;
    p[0]=n0*s; p[1]=n1*s; p[2]=n2*s;
    float q0=n0*m[0]+n1*m[3]+n2*m[6];
    float q1=n0*m[1]+n1*m[4]+n2*m[7];
    float q2=n0*m[2]+n1*m[5]+n2*m[8];
    m[0]-=2.f*n0*q0; m[1]-=2.f*n0*q1; m[2]-=2.f*n0*q2;
    m[3]-=2.f*n1*q0; m[4]-=2.f*n1*q1; m[5]-=2.f*n1*q2;
    m[6]-=2.f*n2*q0; m[7]-=2.f*n2*q1; m[8]-=2.f*n2*q2;
  }
}

__device__ __forceinline__ void pre_step(const PS& s, const float* s_jm,
    const float* s_cr, float jv, float sv, int& drt, int& ridx, float* T){
  ridx = min(max(s.rt-10,0),10);
  drt = 0;
  if(jv < s_cr[ridx]*DT){
    const float* row=s_jm+ridx*20; int c=0;
    #pragma unroll
    for(int j=0;j<20;j++) c += (sv<row[j]) ? 1 : 0;
    int ind=20-c;
    drt = (ind<10) ? (ind+1) : (-(ind-9));
  }
  float dot=s.xt[0]*s.xt[0]+s.xt[1]*s.xt[1]+s.xt[2]*s.xt[2];
  float aa=fminf(fmaxf(s.xt[2]*rsqrtf(fmaxf(dot,1e-24f)),-1.f),1.f);
  float st=-aa, ct=sqrtf(fmaxf(1.f-aa*aa,0.f));
  float dxy=s.xt[0]*s.xt[0]+s.xt[1]*s.xt[1];
  float cp,sp;
  if(dxy>0.f){
    float inv=rsqrtf(dxy);
    cp=s.xt[0]*inv; sp=s.xt[1]*inv;
  } else { cp=1.f; sp=0.f; }
  T[0]=cp*ct; T[1]=-sp;  T[2]=cp*st;
  T[3]=sp*ct; T[4]=cp;   T[5]=sp*st;
  T[6]=-st;   T[7]=0.f;  T[8]=ct;
}

__device__ __forceinline__ bool post_step(PS& s, const float* T, const float* gu,
    float jump, float db0, float db1, float dy0, float dy1, float dy2,
    int drt, int ridx, const float* s_cfr, const float* s_inv){
  float v0=gu[0]*s.gx[0]+gu[1]*s.gx[3]+gu[2]*s.gx[6];
  float v1=gu[0]*s.gx[1]+gu[1]*s.gx[4]+gu[2]*s.gx[7];
  float v2=gu[0]*s.gx[2]+gu[1]*s.gx[5]+gu[2]*s.gx[8];
  float w1=v0*T[1]+v1*T[4]+v2*T[7];
  float w2=v0*T[2]+v1*T[5]+v2*T[8];
  float gux0=-w2, gux1=w1;
  float q0=gu[3]*s.gy[0]+gu[4]*s.gy[3]+gu[5]*s.gy[6];
  float q1=gu[3]*s.gy[1]+gu[4]*s.gy[4]+gu[5]*s.gy[7];
  float q2=gu[3]*s.gy[2]+gu[4]*s.gy[5]+gu[5]*s.gy[8];
  float sdx=s_inv[s.rt-10];
  float diff=sdx*(gux0*db0+gux1*db1)+(q0*dy0+q1*dy1+q2*dy2)+jump;
  s.up += __expf(-s.fun)*diff;
  s.fun += s_cfr[ridx]*DT;
  float dX0=sdx*db0, dX1=sdx*db1;
  float x2=dX0*dX0;
  float s_t = 1.f - x2*(0.5f - x2*(0.0416666667f - x2*0.00138888889f));
  float c_t = -dX0*(1.f - x2*(0.166666667f - x2*(0.00833333333f - x2*1.98412698e-4f)));
  float y2=dX1*dX1;
  float c_p = 1.f - y2*(0.5f - y2*(0.0416666667f - y2*0.00138888889f));
  float s_p = dX1*(1.f - y2*(0.166666667f - y2*(0.00833333333f - y2*1.98412698e-4f)));
  float cx=s_t*c_p-1.f, cy=s_t*s_p, cz=c_t;
  float d0=T[0]*cx+T[1]*cy+T[2]*cz;
  float d1=T[3]*cx+T[4]*cy+T[5]*cz;
  float d2=T[6]*cx+T[7]*cy+T[8]*cz;
  s.xt[0]+=d0; s.xt[1]+=d1; s.xt[2]+=d2;
  s.xi[0]+=s.gx[0]*d0+s.gx[1]*d1+s.gx[2]*d2;
  s.xi[1]+=s.gx[3]*d0+s.gx[4]*d1+s.gx[5]*d2;
  s.xi[2]+=s.gx[6]*d0+s.gx[7]*d1+s.gx[8]*d2;
  s.yi[0]+=s.gy[0]*dy0+s.gy[1]*dy1+s.gy[2]*dy2;
  s.yi[1]+=s.gy[3]*dy0+s.gy[4]*dy1+s.gy[5]*dy2;
  s.yi[2]+=s.gy[6]*dy0+s.gy[7]*dy1+s.gy[8]*dy2;
  s.rt=min(max(s.rt+drt,10),20);
  refl(s.xi,s.gx); refl(s.yi,s.gy);
  float e0=s.xi[0]-s.yi[0], e1=s.xi[1]-s.yi[1], e2=s.xi[2]-s.yi[2];
  return sqrtf(e0*e0+e1*e1+e2*e2)<0.1f;
}

__global__ void __launch_bounds__(128) kmain(
  const float* __restrict__ u, const float* __restrict__ jm,
  const float* __restrict__ cr, const float* __restrict__ cfr,
  const int* __restrict__ rt0, const float* __restrict__ xt0,
  const float* __restrict__ yt0, const float* __restrict__ dBx,
  const float* __restrict__ dBy, const float* __restrict__ juf,
  const float* __restrict__ suf, float* __restrict__ out)
{
  int tid=threadIdx.x, l=tid&31, wl=tid>>5;
  int wp=blockIdx.x*4+wl;
  int pA=2*wp, pB=2*wp+1;
  __shared__ __align__(16) float2 shA[4][HH];
  __shared__ __align__(16) float2 shB[4][HH];
  __shared__ float s_jm[NR*20];
  __shared__ float s_cr[NR], s_cfr[NR], s_inv[NR];
  for(int i=tid;i<NR*20;i+=128) s_jm[i]=jm[i];
  if(tid<NR){
    s_cr[tid]=cr[tid]; s_cfr[tid]=cfr[tid];
    s_inv[tid]=1.0f/(float)(tid+10);
  }
  __syncthreads();

  PS A, B;
  A.rt=rt0[pA]; B.rt=rt0[pB];
  #pragma unroll
  for(int k=0;k<3;k++){
    A.xt[k]=xt0[pA*3+k]; A.xi[k]=A.xt[k]; A.yi[k]=yt0[pA*3+k];
    B.xt[k]=xt0[pB*3+k]; B.xi[k]=B.xt[k]; B.yi[k]=yt0[pB*3+k];
  }
  #pragma unroll
  for(int k=0;k<9;k++){
    float id=(k==0||k==4||k==8)?1.f:0.f;
    A.gx[k]=id; A.gy[k]=id; B.gx[k]=id; B.gy[k]=id;
  }
  float u0=u[0];
  A.up=u0; B.up=u0; A.fun=0.f; B.fun=0.f; A.act=1; B.act=1;

  // noise prefetch (t=0)
  float2 ju2=*(const float2*)(juf + pA);
  float2 su2=*(const float2*)(suf + pA);
  float4 dbx4=*(const float4*)(dBx + (size_t)pA*2);
  const float* dyp0 = dBy + (size_t)pA*3;
  float2 dya=*(const float2*)(dyp0);
  float2 dym=*(const float2*)(dyp0+2);
  float2 dyb=*(const float2*)(dyp0+4);

  for(int t=0;t<NS;t++){
    // prefetch t+1 noise (hidden under this step's compute)
    float2 ju2n, su2n, dyan, dymn, dybn; float4 dbx4n;
    if(t+1<NS){
      int base=(t+1)*NB+pA;
      ju2n=*(const float2*)(juf + base);
      su2n=*(const float2*)(suf + base);
      dbx4n=*(const float4*)(dBx + (size_t)base*2);
      const float* dyp = dBy + (size_t)base*3;
      dyan=*(const float2*)(dyp);
      dymn=*(const float2*)(dyp+2);
      dybn=*(const float2*)(dyp+4);
    }
    float dyA0=dya.x, dyA1=dya.y, dyA2=dym.x;
    float dyB0=dym.y, dyB1=dyb.x, dyB2=dyb.y;

    int drtA,ridxA,drtB,ridxB;
    float TA[9], TB[9];
    pre_step(A,s_jm,s_cr,ju2.x,su2.x,drtA,ridxA,TA);
    pre_step(B,s_jm,s_cr,ju2.y,su2.y,drtB,ridxB,TB);

    float in6A[6]={A.xi[0],A.xi[1],A.xi[2],A.yi[0],A.yi[1],A.yi[2]};
    float in6B[6]={B.xi[0],B.xi[1],B.xi[2],B.yi[0],B.yi[1],B.yi[2]};

    float4 bb=g_Pb[t*32+l];
    float4 a1A=bb, a1B=bb;
    {
      const float4* Wp=g_P1+t*6*32;
      #pragma unroll
      for(int i=0;i<6;i++){
        float4 wv=Wp[i*32+l];
        a1A.x+=in6A[i]*wv.x; a1A.y+=in6A[i]*wv.y;
        a1A.z+=in6A[i]*wv.z; a1A.w+=in6A[i]*wv.w;
        a1B.x+=in6B[i]*wv.x; a1B.y+=in6B[i]*wv.y;
        a1B.z+=in6B[i]*wv.z; a1B.w+=in6B[i]*wv.w;
      }
    }
    ((float4*)shA[wl])[l]=make_float4(tanh_(a1A.x),tanh_(a1A.z),tanh_(a1A.y),tanh_(a1A.w));
    ((float4*)shB[wl])[l]=make_float4(tanh_(a1B.x),tanh_(a1B.z),tanh_(a1B.y),tanh_(a1B.w));
    __syncwarp();
    float4 b2v=g_Pb2[t*32+l];
    float4 a2A=b2v, a2B=b2v;
    {
      const float4* Wp=g_P2+t*HH*32;
      #pragma unroll 8
      for(int i=0;i<HH;i++){
        float2 xA=shA[wl][i];
        float2 xB=shB[wl][i];
        float4 wv=Wp[i*32+l];
        a2A.x+=xA.x*wv.x; a2A.y+=xA.x*wv.y;
        a2A.z+=xA.y*wv.z; a2A.w+=xA.y*wv.w;
        a2B.x+=xB.x*wv.x; a2B.y+=xB.x*wv.y;
        a2B.z+=xB.y*wv.z; a2B.w+=xB.y*wv.w;
      }
    }
    __syncwarp();
    float2 h2A=make_float2(tanh_(a2A.x),tanh_(a2A.y));
    float2 f2A=make_float2(tanh_(a2A.z),tanh_(a2A.w));
    float2 h2B=make_float2(tanh_(a2B.x),tanh_(a2B.y));
    float2 f2B=make_float2(tanh_(a2B.z),tanh_(a2B.w));
    int cA=drtA+10, cB=drtB+10;
    float v[14];
    {
      const float* WpA=g_W3+(t*NR+ridxA)*6*HH;
      const float* WpB=g_W3+(t*NR+ridxB)*6*HH;
      #pragma unroll
      for(int o=0;o<6;o++){
        float2 wa=*(const float2*)(WpA+o*HH+2*l);
        float2 wb=*(const float2*)(WpB+o*HH+2*l);
        v[o]  =h2A.x*wa.x+h2A.y*wa.y;
        v[7+o]=h2B.x*wb.x+h2B.y*wb.y;
      }
      float2 aa2=*(const float2*)(g_A+(t*RC+ridxA*21+cA)*HH+2*l);
      float2 ab2=*(const float2*)(g_A+(t*RC+ridxB*21+cB)*HH+2*l);
      v[6] =f2A.x*aa2.x+f2A.y*aa2.y;
      v[13]=f2B.x*ab2.x+f2B.y*ab2.y;
    }
    #pragma unroll
    for(int k=16;k;k>>=1){
      #pragma unroll
      for(int j=0;j<14;j++) v[j]+=__shfl_xor_sync(0xffffffffu,v[j],k);
    }
    float guA[6], guB[6];
    {
      const float* bpA=g_b3+(t*NR+ridxA)*6;
      const float* bpB=g_b3+(t*NR+ridxB)*6;
      #pragma unroll
      for(int o=0;o<6;o++){ guA[o]=v[o]+bpA[o]; guB[o]=v[7+o]+bpB[o]; }
    }
    float jumpA=v[6]+g_B[t*RC+ridxA*21+cA];
    float jumpB=v[13]+g_B[t*RC+ridxB*21+cB];

    if(A.act){
      if(post_step(A,TA,guA,jumpA,dbx4.x,dbx4.y,dyA0,dyA1,dyA2,drtA,ridxA,s_cfr,s_inv)) A.act=0;
    }
    if(B.act){
      if(post_step(B,TB,guB,jumpB,dbx4.z,dbx4.w,dyB0,dyB1,dyB2,drtB,ridxB,s_cfr,s_inv)) B.act=0;
    }
    if(!A.act && !B.act) break;
    ju2=ju2n; su2=su2n; dbx4=dbx4n; dya=dyan; dym=dymn; dyb=dybn;
  }
  if(l==0){
    float e0=A.xi[0]-A.yi[0], e1=A.xi[1]-A.yi[1], e2=A.xi[2]-A.yi[2];
    out[pA]=A.up;
    out[NB+pA]=A.act ? __expf(-(e0*e0+e1*e1+e2*e2))*__expf(-A.fun) : 0.f;
    e0=B.xi[0]-B.yi[0]; e1=B.xi[1]-B.yi[1]; e2=B.xi[2]-B.yi[2];
    out[pB]=B.up;
    out[NB+pB]=B.act ? __expf(-(e0*e0+e1*e1+e2*e2))*__expf(-B.fun) : 0.f;
  }
}

extern "C" void kernel_launch(void* const* d_in, const int* in_sizes, int n_in,
                              void* d_out, int out_size) {
  const float* u   =(const float*)d_in[0];
  const float* jr  =(const float*)d_in[1];
  const float* jl  =(const float*)d_in[2];
  const float* W1  =(const float*)d_in[3];
  const float* b1  =(const float*)d_in[4];
  const float* W2  =(const float*)d_in[5];
  const float* b2  =(const float*)d_in[6];
  const float* W3  =(const float*)d_in[7];
  const float* b3  =(const float*)d_in[8];
  const float* emb =(const float*)d_in[9];
  const float* Wf1 =(const float*)d_in[10];
  const float* bf1 =(const float*)d_in[11];
  const float* Wf2 =(const float*)d_in[12];
  const float* bf2 =(const float*)d_in[13];
  const float* Wf3 =(const float*)d_in[14];
  const float* bf3 =(const float*)d_in[15];
  const int*   rt0 =(const int*)  d_in[16];
  const float* xt0 =(const float*)d_in[17];
  const float* yt0 =(const float*)d_in[18];
  const float* dBx =(const float*)d_in[19];
  const float* dBy =(const float*)d_in[20];
  const float* juf =(const float*)d_in[21];
  const float* suf =(const float*)d_in[22];
  const float* mcu =(const float*)d_in[23];
  const float* jm  =(const float*)d_in[24];
  const float* cr  =(const float*)d_in[25];
  const float* cfr =(const float*)d_in[26];

  kz<<<1,256>>>();
  kh<<<(MCN*NR+255)/256,256>>>(mcu,jm);
  kw<<<RC,HP>>>(jl,jr,cr);
  kA2B<<<dim3(NS,8),256>>>(Wf3,bf3);
  kEP<<<NS,384>>>(W3,emb,b3,W1,b1,W2,b2,Wf1,bf1,Wf2,bf2);
  kmain<<<NB/8,128>>>(u,jm,cr,cfr,rt0,xt0,yt0,dBx,dBy,juf,suf,(float*)d_out);
}

// round 9
// speedup vs baseline: 2.3563x; 2.3563x over previous
#include <cuda_runtime.h>

#define NS 64
#define NB 8192
#define HP 128
#define HH 64
#define NR 11
#define RC 231
#define GAPN 10
#define MCN 10000
#define DT (1.0f/64.0f)

__device__ int   g_hist[NR*20];
__device__ __align__(16) float g_wtab[RC*HP];
__device__ __align__(16) float g_A[NS*RC*HH];
__device__ __align__(16) float g_B[NS*RC];
__device__ __align__(16) float g_W3[NS*NR*6*HH];
__device__ __align__(16) float g_b3[NS*NR*6];
__device__ float4 g_P1[NS*6*32];
__device__ float4 g_P2[NS*HH*32];
__device__ float4 g_Pb[NS*32];
__device__ float4 g_Pb2[NS*32];

__global__ void kz(){ int i=threadIdx.x; if(i<NR*20) g_hist[i]=0; }

__global__ void kh(const float* __restrict__ mc, const float* __restrict__ jm){
  __shared__ int sh[NR*20];
  int tid=threadIdx.x;
  if(tid<NR*20) sh[tid]=0;
  __syncthreads();
  int i=blockIdx.x*blockDim.x+tid;
  if(i<MCN*NR){
    int r=i%NR; float u=mc[i]; const float* row=jm+r*20; int c=0;
    #pragma unroll
    for(int j=0;j<20;j++) c += (u<row[j]) ? 1 : 0;
    atomicAdd(&sh[r*20+(20-c)],1);
  }
  __syncthreads();
  if(tid<NR*20 && sh[tid]) atomicAdd(&g_hist[tid],sh[tid]);
}

__global__ void kw(const float* __restrict__ jl, const float* __restrict__ jr,
                   const float* __restrict__ cr){
  int r=blockIdx.x/21, c=blockIdx.x%21, p=threadIdx.x;
  float acc=0.f;
  #pragma unroll
  for(int k=0;k<GAPN;k++){
    acc += (float)g_hist[r*20+k]    * jl[k*HP+p];
    acc += (float)g_hist[r*20+10+k] * jl[(GAPN+k)*HP+p];
  }
  float mc_ = cr[r]*(acc*(1.0f/MCN));
  int d=c-10; float j=0.f;
  if(d>0) j=jl[(d-1)*HP+p]; else if(d<0) j=jl[(GAPN+(-d-1))*HP+p];
  g_wtab[(r*21+c)*HP+p] = jr[r*HP+p]*(j - mc_*DT);
}

__global__ void __launch_bounds__(256) kA2B(const float* __restrict__ Wf3,
                                            const float* __restrict__ bf3){
  int t=blockIdx.x, chunk=blockIdx.y;
  __shared__ float sW[HP*65];
  __shared__ float swt[4][HP];
  __shared__ float sb[HP];
  int tid=threadIdx.x;
  for(int idx=tid; idx<HH*HP; idx+=256){
    int h=idx>>7, p=idx&127;
    sW[p*65+h]=Wf3[t*HH*HP+idx];
  }
  if(tid<HP) sb[tid]=bf3[t*HP+tid];
  __syncthreads();
  int h=tid&63, g=tid>>6;
  int rcEnd=min(chunk*29+29,RC);
  for(int rc0=chunk*29; rc0<rcEnd; rc0+=4){
    __syncthreads();
    for(int idx=tid; idx<4*HP; idx+=256){
      int gg=idx>>7, p=idx&127; int rc=rc0+gg;
      swt[gg][p] = (rc<RC) ? g_wtab[rc*HP+p] : 0.f;
    }
    __syncthreads();
    int rc=rc0+g;
    if(rc<rcEnd){
      float a=0.f;
      #pragma unroll 8
      for(int p=0;p<HP;p++) a += sW[p*65+h]*swt[g][p];
      g_A[(t*RC+rc)*HH+h]=a;
    }
    if(tid<4 && rc0+tid<rcEnd){
      float b0=0.f,b1=0.f;
      #pragma unroll 8
      for(int p=0;p<HP;p+=2){ b0+=sb[p]*swt[tid][p]; b1+=sb[p+1]*swt[tid][p+1]; }
      g_B[t*RC+rc0+tid]=b0+b1;
    }
  }
}

__global__ void __launch_bounds__(384) kEP(const float* __restrict__ W3,
                                           const float* __restrict__ emb,
                                           const float* __restrict__ b3,
  const float* __restrict__ W1, const float* __restrict__ b1,
  const float* __restrict__ W2, const float* __restrict__ b2,
  const float* __restrict__ Wf1, const float* __restrict__ bf1,
  const float* __restrict__ Wf2, const float* __restrict__ bf2){
  int t=blockIdx.x, tid=threadIdx.x;
  __shared__ float se[NR*HP];
  for(int i=tid;i<NR*HP;i+=384) se[i]=emb[t*NR*HP+i];
  __syncthreads();
  int h=tid/6, o=tid-h*6;
  float acc[NR];
  #pragma unroll
  for(int r=0;r<NR;r++) acc[r]=0.f;
  const float* W=W3+t*HH*768+h*768+o;
  for(int p=0;p<HP;p++){
    float wv=W[p*6];
    #pragma unroll
    for(int r=0;r<NR;r++) acc[r] += se[r*HP+p]*wv;
  }
  #pragma unroll
  for(int r=0;r<NR;r++) g_W3[((t*NR+r)*6+o)*HH+h]=acc[r];
  if(tid<6){
    float a2[NR];
    #pragma unroll
    for(int r=0;r<NR;r++) a2[r]=0.f;
    const float* bb=b3+t*768+tid;
    for(int p=0;p<HP;p++){
      float bv=bb[p*6];
      #pragma unroll
      for(int r=0;r<NR;r++) a2[r] += se[r*HP+p]*bv;
    }
    #pragma unroll
    for(int r=0;r<NR;r++) g_b3[(t*NR+r)*6+tid]=a2[r];
  }
  for(int idx=tid; idx<HH*32; idx+=384){
    int i=idx>>5, l=idx&31; int b=t*HH*HH+i*HH+2*l;
    g_P2[(t*HH+i)*32+l]=make_float4(W2[b],W2[b+1],Wf2[b],Wf2[b+1]);
  }
  for(int idx=tid; idx<6*32; idx+=384){
    int i=idx>>5, l=idx&31; int b=t*6*HH+i*HH+2*l;
    g_P1[(t*6+i)*32+l]=make_float4(W1[b],W1[b+1],Wf1[b],Wf1[b+1]);
  }
  if(tid<32){
    int b=t*HH+2*tid;
    g_Pb [t*32+tid]=make_float4(b1[b],b1[b+1],bf1[b],bf1[b+1]);
    g_Pb2[t*32+tid]=make_float4(b2[b],b2[b+1],bf2[b],bf2[b+1]);
  }
}

__device__ __forceinline__ float tanh_(float x){
  float e=__expf(2.f*x); return 1.f-__fdividef(2.f,e+1.f);
}

struct PS {
  int rt; int act;
  float xt[3], xi[3], yi[3];
  float gx[9], gy[9];
  float up, fun;
};

__device__ __forceinline__ void refl(float* p, float* m){
  float nr=sqrtf(p[0]*p[0]+p[1]*p[1]+p[2]*p[2]);
  if(nr>5.0f){
    float d=fmaxf(nr,1e-12f);
    float n0=p[0]/d, n1=p[1]/d, n2=p[2]/d;
    float s=10.0f-nr;
    p[0]=n0*s; p[1]=n1*s; p[2]=n2*s;
    float q0=n0*m[0]+n1*m[3]+n2*m[6];
    float q1=n0*m[1]+n1*m[4]+n2*m[7];
    float q2=n0*m[2]+n1*m[5]+n2*m[8];
    m[0]-=2.f*n0*q0; m[1]-=2.f*n0*q1; m[2]-=2.f*n0*q2;
    m[3]-=2.f*n1*q0; m[4]-=2.f*n1*q1; m[5]-=2.f*n1*q2;
    m[6]-=2.f*n2*q0; m[7]-=2.f*n2*q1; m[8]-=2.f*n2*q2;
  }
}

// only jump decision: tiny live state (drt, ridx)
__device__ __forceinline__ void pre_step(const PS& s, const float* s_jm,
    const float* s_cr, float jv, float sv, int& drt, int& ridx){
  ridx = min(max(s.rt-10,0),10);
  drt = 0;
  if(jv < s_cr[ridx]*DT){
    const float* row=s_jm+ridx*20; int c=0;
    #pragma unroll
    for(int j=0;j<20;j++) c += (sv<row[j]) ? 1 : 0;
    int ind=20-c;
    drt = (ind<10) ? (ind+1) : (-(ind-9));
  }
}

// T recomputed here from s.xt (18 fewer live regs across the MLP)
__device__ __forceinline__ bool post_step(PS& s, const float* gu,
    float jump, float db0, float db1, float dy0, float dy1, float dy2,
    int drt, int ridx, const float* s_cfr, const float* s_inv){
  float dot=s.xt[0]*s.xt[0]+s.xt[1]*s.xt[1]+s.xt[2]*s.xt[2];
  float aa=fminf(fmaxf(s.xt[2]*rsqrtf(fmaxf(dot,1e-24f)),-1.f),1.f);
  float st=-aa, ct=sqrtf(fmaxf(1.f-aa*aa,0.f));
  float dxy=s.xt[0]*s.xt[0]+s.xt[1]*s.xt[1];
  float cp,sp;
  if(dxy>0.f){
    float inv=rsqrtf(dxy);
    cp=s.xt[0]*inv; sp=s.xt[1]*inv;
  } else { cp=1.f; sp=0.f; }
  float T[9]={cp*ct,-sp,cp*st, sp*ct,cp,sp*st, -st,0.f,ct};

  float v0=gu[0]*s.gx[0]+gu[1]*s.gx[3]+gu[2]*s.gx[6];
  float v1=gu[0]*s.gx[1]+gu[1]*s.gx[4]+gu[2]*s.gx[7];
  float v2=gu[0]*s.gx[2]+gu[1]*s.gx[5]+gu[2]*s.gx[8];
  float w1=v0*T[1]+v1*T[4]+v2*T[7];
  float w2=v0*T[2]+v1*T[5]+v2*T[8];
  float gux0=-w2, gux1=w1;
  float q0=gu[3]*s.gy[0]+gu[4]*s.gy[3]+gu[5]*s.gy[6];
  float q1=gu[3]*s.gy[1]+gu[4]*s.gy[4]+gu[5]*s.gy[7];
  float q2=gu[3]*s.gy[2]+gu[4]*s.gy[5]+gu[5]*s.gy[8];
  float sdx=s_inv[s.rt-10];
  float diff=sdx*(gux0*db0+gux1*db1)+(q0*dy0+q1*dy1+q2*dy2)+jump;
  s.up += __expf(-s.fun)*diff;
  s.fun += s_cfr[ridx]*DT;
  float dX0=sdx*db0, dX1=sdx*db1;
  float x2=dX0*dX0;
  float s_t = 1.f - x2*(0.5f - x2*(0.0416666667f - x2*0.00138888889f));
  float c_t = -dX0*(1.f - x2*(0.166666667f - x2*(0.00833333333f - x2*1.98412698e-4f)));
  float y2=dX1*dX1;
  float c_p = 1.f - y2*(0.5f - y2*(0.0416666667f - y2*0.00138888889f));
  float s_p = dX1*(1.f - y2*(0.166666667f - y2*(0.00833333333f - y2*1.98412698e-4f)));
  float cx=s_t*c_p-1.f, cy=s_t*s_p, cz=c_t;
  float d0=T[0]*cx+T[1]*cy+T[2]*cz;
  float d1=T[3]*cx+T[4]*cy+T[5]*cz;
  float d2=T[6]*cx+T[7]*cy+T[8]*cz;
  s.xt[0]+=d0; s.xt[1]+=d1; s.xt[2]+=d2;
  s.xi[0]+=s.gx[0]*d0+s.gx[1]*d1+s.gx[2]*d2;
  s.xi[1]+=s.gx[3]*d0+s.gx[4]*d1+s.gx[5]*d2;
  s.xi[2]+=s.gx[6]*d0+s.gx[7]*d1+s.gx[8]*d2;
  s.yi[0]+=s.gy[0]*dy0+s.gy[1]*dy1+s.gy[2]*dy2;
  s.yi[1]+=s.gy[3]*dy0+s.gy[4]*dy1+s.gy[5]*dy2;
  s.yi[2]+=s.gy[6]*dy0+s.gy[7]*dy1+s.gy[8]*dy2;
  s.rt=min(max(s.rt+drt,10),20);
  refl(s.xi,s.gx); refl(s.yi,s.gy);
  float e0=s.xi[0]-s.yi[0], e1=s.xi[1]-s.yi[1], e2=s.xi[2]-s.yi[2];
  return sqrtf(e0*e0+e1*e1+e2*e2)<0.1f;
}

__global__ void __launch_bounds__(128) kmain(
  const float* __restrict__ u, const float* __restrict__ jm,
  const float* __restrict__ cr, const float* __restrict__ cfr,
  const int* __restrict__ rt0, const float* __restrict__ xt0,
  const float* __restrict__ yt0, const float* __restrict__ dBx,
  const float* __restrict__ dBy, const float* __restrict__ juf,
  const float* __restrict__ suf, float* __restrict__ out)
{
  int tid=threadIdx.x, l=tid&31, wl=tid>>5;
  int wp=blockIdx.x*4+wl;
  int pA=2*wp, pB=2*wp+1;
  __shared__ __align__(16) float2 shA[4][HH];
  __shared__ __align__(16) float2 shB[4][HH];
  __shared__ float s_jm[NR*20];
  __shared__ float s_cr[NR], s_cfr[NR], s_inv[NR];
  for(int i=tid;i<NR*20;i+=128) s_jm[i]=jm[i];
  if(tid<NR){
    s_cr[tid]=cr[tid]; s_cfr[tid]=cfr[tid];
    s_inv[tid]=1.0f/(float)(tid+10);
  }
  __syncthreads();

  PS A, B;
  A.rt=rt0[pA]; B.rt=rt0[pB];
  #pragma unroll
  for(int k=0;k<3;k++){
    A.xt[k]=xt0[pA*3+k]; A.xi[k]=A.xt[k]; A.yi[k]=yt0[pA*3+k];
    B.xt[k]=xt0[pB*3+k]; B.xi[k]=B.xt[k]; B.yi[k]=yt0[pB*3+k];
  }
  #pragma unroll
  for(int k=0;k<9;k++){
    float id=(k==0||k==4||k==8)?1.f:0.f;
    A.gx[k]=id; A.gy[k]=id; B.gx[k]=id; B.gy[k]=id;
  }
  float u0=u[0];
  A.up=u0; B.up=u0; A.fun=0.f; B.fun=0.f; A.act=1; B.act=1;

  for(int t=0;t<NS;t++){
    float2 ju2=*(const float2*)(juf + t*NB + pA);
    float2 su2=*(const float2*)(suf + t*NB + pA);
    float4 dbx4=*(const float4*)(dBx + (size_t)(t*NB+pA)*2);
    const float* dyp = dBy + (size_t)(t*NB+pA)*3;
    float2 dya=*(const float2*)(dyp);
    float2 dym=*(const float2*)(dyp+2);
    float2 dyb=*(const float2*)(dyp+4);
    float dyA0=dya.x, dyA1=dya.y, dyA2=dym.x;
    float dyB0=dym.y, dyB1=dyb.x, dyB2=dyb.y;

    int drtA,ridxA,drtB,ridxB;
    pre_step(A,s_jm,s_cr,ju2.x,su2.x,drtA,ridxA);
    pre_step(B,s_jm,s_cr,ju2.y,su2.y,drtB,ridxB);

    float in6A[6]={A.xi[0],A.xi[1],A.xi[2],A.yi[0],A.yi[1],A.yi[2]};
    float in6B[6]={B.xi[0],B.xi[1],B.xi[2],B.yi[0],B.yi[1],B.yi[2]};

    float4 bb=g_Pb[t*32+l];
    float4 a1A=bb, a1B=bb;
    {
      const float4* Wp=g_P1+t*6*32;
      #pragma unroll
      for(int i=0;i<6;i++){
        float4 wv=Wp[i*32+l];
        a1A.x+=in6A[i]*wv.x; a1A.y+=in6A[i]*wv.y;
        a1A.z+=in6A[i]*wv.z; a1A.w+=in6A[i]*wv.w;
        a1B.x+=in6B[i]*wv.x; a1B.y+=in6B[i]*wv.y;
        a1B.z+=in6B[i]*wv.z; a1B.w+=in6B[i]*wv.w;
      }
    }
    ((float4*)shA[wl])[l]=make_float4(tanh_(a1A.x),tanh_(a1A.z),tanh_(a1A.y),tanh_(a1A.w));
    ((float4*)shB[wl])[l]=make_float4(tanh_(a1B.x),tanh_(a1B.z),tanh_(a1B.y),tanh_(a1B.w));
    __syncwarp();
    float4 b2v=g_Pb2[t*32+l];
    float4 a2A=b2v, a2B=b2v;
    {
      const float4* Wp=g_P2+t*HH*32;
      #pragma unroll 8
      for(int i=0;i<HH;i++){
        float2 xA=shA[wl][i];
        float2 xB=shB[wl][i];
        float4 wv=Wp[i*32+l];
        a2A.x+=xA.x*wv.x; a2A.y+=xA.x*wv.y;
        a2A.z+=xA.y*wv.z; a2A.w+=xA.y*wv.w;
        a2B.x+=xB.x*wv.x; a2B.y+=xB.x*wv.y;
        a2B.z+=xB.y*wv.z; a2B.w+=xB.y*wv.w;
      }
    }
    __syncwarp();
    float2 h2A=make_float2(tanh_(a2A.x),tanh_(a2A.y));
    float2 f2A=make_float2(tanh_(a2A.z),tanh_(a2A.w));
    float2 h2B=make_float2(tanh_(a2B.x),tanh_(a2B.y));
    float2 f2B=make_float2(tanh_(a2B.z),tanh_(a2B.w));
    int cA=drtA+10, cB=drtB+10;
    float v[14];
    {
      const float* WpA=g_W3+(t*NR+ridxA)*6*HH;
      const float* WpB=g_W3+(t*NR+ridxB)*6*HH;
      #pragma unroll
      for(int o=0;o<6;o++){
        float2 wa=*(const float2*)(WpA+o*HH+2*l);
        float2 wb=*(const float2*)(WpB+o*HH+2*l);
        v[o]  =h2A.x*wa.x+h2A.y*wa.y;
        v[7+o]=h2B.x*wb.x+h2B.y*wb.y;
      }
      float2 aa2=*(const float2*)(g_A+(t*RC+ridxA*21+cA)*HH+2*l);
      float2 ab2=*(const float2*)(g_A+(t*RC+ridxB*21+cB)*HH+2*l);
      v[6] =f2A.x*aa2.x+f2A.y*aa2.y;
      v[13]=f2B.x*ab2.x+f2B.y*ab2.y;
    }
    #pragma unroll
    for(int k=16;k;k>>=1){
      #pragma unroll
      for(int j=0;j<14;j++) v[j]+=__shfl_xor_sync(0xffffffffu,v[j],k);
    }
    float guA[6], guB[6];
    {
      const float* bpA=g_b3+(t*NR+ridxA)*6;
      const float* bpB=g_b3+(t*NR+ridxB)*6;
      #pragma unroll
      for(int o=0;o<6;o++){ guA[o]=v[o]+bpA[o]; guB[o]=v[7+o]+bpB[o]; }
    }
    float jumpA=v[6]+g_B[t*RC+ridxA*21+cA];
    float jumpB=v[13]+g_B[t*RC+ridxB*21+cB];

    if(A.act){
      if(post_step(A,guA,jumpA,dbx4.x,dbx4.y,dyA0,dyA1,dyA2,drtA,ridxA,s_cfr,s_inv)) A.act=0;
    }
    if(B.act){
      if(post_step(B,guB,jumpB,dbx4.z,dbx4.w,dyB0,dyB1,dyB2,drtB,ridxB,s_cfr,s_inv)) B.act=0;
    }
    if(!A.act && !B.act) break;
  }
  if(l==0){
    float e0=A.xi[0]-A.yi[0], e1=A.xi[1]-A.yi[1], e2=A.xi[2]-A.yi[2];
    out[pA]=A.up;
    out[NB+pA]=A.act ? __expf(-(e0*e0+e1*e1+e2*e2))*__expf(-A.fun) : 0.f;
    e0=B.xi[0]-B.yi[0]; e1=B.xi[1]-B.yi[1]; e2=B.xi[2]-B.yi[2];
    out[pB]=B.up;
    out[NB+pB]=B.act ? __expf(-(e0*e0+e1*e1+e2*e2))*__expf(-B.fun) : 0.f;
  }
}

extern "C" void kernel_launch(void* const* d_in, const int* in_sizes, int n_in,
                              void* d_out, int out_size) {
  const float* u   =(const float*)d_in[0];
  const float* jr  =(const float*)d_in[1];
  const float* jl  =(const float*)d_in[2];
  const float* W1  =(const float*)d_in[3];
  const float* b1  =(const float*)d_in[4];
  const float* W2  =(const float*)d_in[5];
  const float* b2  =(const float*)d_in[6];
  const float* W3  =(const float*)d_in[7];
  const float* b3  =(const float*)d_in[8];
  const float* emb =(const float*)d_in[9];
  const float* Wf1 =(const float*)d_in[10];
  const float* bf1 =(const float*)d_in[11];
  const float* Wf2 =(const float*)d_in[12];
  const float* bf2 =(const float*)d_in[13];
  const float* Wf3 =(const float*)d_in[14];
  const float* bf3 =(const float*)d_in[15];
  const int*   rt0 =(const int*)  d_in[16];
  const float* xt0 =(const float*)d_in[17];
  const float* yt0 =(const float*)d_in[18];
  const float* dBx =(const float*)d_in[19];
  const float* dBy =(const float*)d_in[20];
  const float* juf =(const float*)d_in[21];
  const float* suf =(const float*)d_in[22];
  const float* mcu =(const float*)d_in[23];
  const float* jm  =(const float*)d_in[24];
  const float* cr  =(const float*)d_in[25];
  const float* cfr =(const float*)d_in[26];

  kz<<<1,256>>>();
  kh<<<(MCN*NR+255)/256,256>>>(mcu,jm);
  kw<<<RC,HP>>>(jl,jr,cr);
  kA2B<<<dim3(NS,8),256>>>(Wf3,bf3);
  kEP<<<NS,384>>>(W3,emb,b3,W1,b1,W2,b2,Wf1,bf1,Wf2,bf2);
  kmain<<<NB/8,128>>>(u,jm,cr,cfr,rt0,xt0,yt0,dBx,dBy,juf,suf,(float*)d_out);
}